// round 3
// baseline (speedup 1.0000x reference)
#include <cuda_runtime.h>
#include <cstdint>

// out[nat, 48] = segment_sum(x*switch, src) - segment_sum(x*switch, dst)
// E = 1.6M, D = 48, nat = 50k.
// 12 threads per feature-row, 4 adjacent edges per thread:
//   - sw/src/dst fetched as float4/int4 (1 wavefront each instead of 4+)
//   - 8 front-loaded x loads (streaming) for MLP
//   - red.global.add.v4.f32 to L2-resident output

#define D_FEAT 48
#define VECS_PER_EDGE (D_FEAT / 4)   // 12
#define EDGES_PER_THREAD 4

__global__ void zero_out_kernel(float4* __restrict__ out, int n_vec) {
    int i = blockIdx.x * blockDim.x + threadIdx.x;
    if (i < n_vec) out[i] = make_float4(0.f, 0.f, 0.f, 0.f);
}

__device__ __forceinline__ void red_v4(float* p, float a, float b, float c, float d) {
    asm volatile("red.global.add.v4.f32 [%0], {%1,%2,%3,%4};"
                 :: "l"(p), "f"(a), "f"(b), "f"(c), "f"(d) : "memory");
}

__global__ void __launch_bounds__(256)
scatter_edges_kernel(const float4* __restrict__ x4,
                     const float4* __restrict__ sw4,
                     const int4* __restrict__ esrc4,
                     const int4* __restrict__ edst4,
                     float* __restrict__ out,
                     int n_groups) {
    int t = blockIdx.x * blockDim.x + threadIdx.x;
    int total = n_groups * VECS_PER_EDGE;
    if (t >= total) return;

    int g = t / VECS_PER_EDGE;        // edge group: edges 4g..4g+3
    int c = t - g * VECS_PER_EDGE;    // 0..11

    // Vectorized scalar loads: 1 wavefront each across the warp
    float4 s  = __ldg(sw4 + g);
    int4  src = __ldg(esrc4 + g);
    int4  dst = __ldg(edst4 + g);

    // Front-load all x (streaming; zero reuse) for max MLP
    size_t base = (size_t)g * (4 * VECS_PER_EDGE) + c;
    float4 v0 = __ldcs(x4 + base);
    float4 v1 = __ldcs(x4 + base + VECS_PER_EDGE);
    float4 v2 = __ldcs(x4 + base + 2 * VECS_PER_EDGE);
    float4 v3 = __ldcs(x4 + base + 3 * VECS_PER_EDGE);

    float a0x = v0.x * s.x, a0y = v0.y * s.x, a0z = v0.z * s.x, a0w = v0.w * s.x;
    float a1x = v1.x * s.y, a1y = v1.y * s.y, a1z = v1.z * s.y, a1w = v1.w * s.y;
    float a2x = v2.x * s.z, a2y = v2.y * s.z, a2z = v2.z * s.z, a2w = v2.w * s.z;
    float a3x = v3.x * s.w, a3y = v3.y * s.w, a3z = v3.z * s.w, a3w = v3.w * s.w;

    size_t co = (size_t)c * 4;
    red_v4(out + (size_t)src.x * D_FEAT + co,  a0x,  a0y,  a0z,  a0w);
    red_v4(out + (size_t)src.y * D_FEAT + co,  a1x,  a1y,  a1z,  a1w);
    red_v4(out + (size_t)src.z * D_FEAT + co,  a2x,  a2y,  a2z,  a2w);
    red_v4(out + (size_t)src.w * D_FEAT + co,  a3x,  a3y,  a3z,  a3w);
    red_v4(out + (size_t)dst.x * D_FEAT + co, -a0x, -a0y, -a0z, -a0w);
    red_v4(out + (size_t)dst.y * D_FEAT + co, -a1x, -a1y, -a1z, -a1w);
    red_v4(out + (size_t)dst.z * D_FEAT + co, -a2x, -a2y, -a2z, -a2w);
    red_v4(out + (size_t)dst.w * D_FEAT + co, -a3x, -a3y, -a3z, -a3w);
}

extern "C" void kernel_launch(void* const* d_in, const int* in_sizes, int n_in,
                              void* d_out, int out_size) {
    const float4* x4  = (const float4*)d_in[0];   // x [E, 48] fp32
    const float4* sw4 = (const float4*)d_in[1];   // switch [E]
    const int4*   src = (const int4*)d_in[2];     // edge_src [E]
    const int4*   dst = (const int4*)d_in[3];     // edge_dst [E]
    float*        out = (float*)d_out;            // [nat, 48] fp32

    int n_edges = in_sizes[1];
    int n_groups = n_edges / EDGES_PER_THREAD;    // E = 1.6M, divisible by 4
    int n_out_vec = out_size / 4;

    zero_out_kernel<<<(n_out_vec + 255) / 256, 256>>>((float4*)out, n_out_vec);

    int total = n_groups * VECS_PER_EDGE;
    scatter_edges_kernel<<<(total + 255) / 256, 256>>>(x4, sw4, src, dst, out, n_groups);
}

// round 4
// speedup vs baseline: 1.0434x; 1.0434x over previous
#include <cuda_runtime.h>
#include <cstdint>

// out[nat, 48] = segment_sum(x*switch, src) - segment_sum(x*switch, dst)
// E = 1.6M, D = 48, nat = 50k.
// 12 threads per edge, 2 ADJACENT edges per thread:
//   - sw/src/dst fetched as float2/int2 (3 scalar wavefronts instead of 6)
//   - x front-loaded with streaming hint (zero reuse)
//   - red.global.add.v4.f32 to L2-resident output
//   - output zeroed via graph-capturable cudaMemsetAsync

#define D_FEAT 48
#define VECS_PER_EDGE (D_FEAT / 4)   // 12

__device__ __forceinline__ void red_v4(float* p, float a, float b, float c, float d) {
    asm volatile("red.global.add.v4.f32 [%0], {%1,%2,%3,%4};"
                 :: "l"(p), "f"(a), "f"(b), "f"(c), "f"(d) : "memory");
}

__global__ void __launch_bounds__(256)
scatter_edges_kernel(const float4* __restrict__ x4,
                     const float2* __restrict__ sw2,
                     const int2* __restrict__ esrc2,
                     const int2* __restrict__ edst2,
                     float* __restrict__ out,
                     int n_pairs) {
    int t = blockIdx.x * blockDim.x + threadIdx.x;
    int total = n_pairs * VECS_PER_EDGE;
    if (t >= total) return;

    int g = t / VECS_PER_EDGE;        // edge pair: edges 2g, 2g+1
    int c = t - g * VECS_PER_EDGE;    // 0..11

    // Paired scalar loads: 1 wavefront each across the 12-lane group
    float2 s  = __ldg(sw2 + g);
    int2  src = __ldg(esrc2 + g);
    int2  dst = __ldg(edst2 + g);

    // Front-load x (streaming; zero reuse) for MLP
    size_t base = (size_t)g * (2 * VECS_PER_EDGE) + c;
    float4 v0 = __ldcs(x4 + base);
    float4 v1 = __ldcs(x4 + base + VECS_PER_EDGE);

    float ax = v0.x * s.x, ay = v0.y * s.x, az = v0.z * s.x, aw = v0.w * s.x;
    float bx = v1.x * s.y, by = v1.y * s.y, bz = v1.z * s.y, bw = v1.w * s.y;

    size_t co = (size_t)c * 4;
    red_v4(out + (size_t)src.x * D_FEAT + co,  ax,  ay,  az,  aw);
    red_v4(out + (size_t)src.y * D_FEAT + co,  bx,  by,  bz,  bw);
    red_v4(out + (size_t)dst.x * D_FEAT + co, -ax, -ay, -az, -aw);
    red_v4(out + (size_t)dst.y * D_FEAT + co, -bx, -by, -bz, -bw);
}

extern "C" void kernel_launch(void* const* d_in, const int* in_sizes, int n_in,
                              void* d_out, int out_size) {
    const float4* x4  = (const float4*)d_in[0];   // x [E, 48] fp32
    const float2* sw2 = (const float2*)d_in[1];   // switch [E]
    const int2*   src = (const int2*)d_in[2];     // edge_src [E]
    const int2*   dst = (const int2*)d_in[3];     // edge_dst [E]
    float*        out = (float*)d_out;            // [nat, 48] fp32

    int n_edges = in_sizes[1];
    int n_pairs = n_edges / 2;                    // E = 1.6M, even

    cudaMemsetAsync(out, 0, (size_t)out_size * sizeof(float));

    int total = n_pairs * VECS_PER_EDGE;
    scatter_edges_kernel<<<(total + 255) / 256, 256>>>(x4, sw2, src, dst, out, n_pairs);
}